// round 8
// baseline (speedup 1.0000x reference)
#include <cuda_runtime.h>
#include <cuda_bf16.h>
#include <mma.h>
#include <cstdint>

using namespace nvcuda;

// Problem constants
#define NROWS   262144        // 16 * 16384
#define DIM     64
#define SUB     256
#define MTILE   256           // rows per block
#define NBLK    1024          // NROWS / MTILE
#define MARGIN  3.0e-5f

// Output layout (float32): [z_q_out: 16*64*16384][loss][perplexity][idx: 262144]
#define ZQ_OFF   0
#define LOSS_OFF 16777216
#define PERP_OFF 16777217
#define IDX_OFF  16777218

// Shared bf16 tile stride (72 bf16 = 144B; 16B units rotate by 9 -> conflict-free ldmatrix)
#define TSTR 72
// D scratch stride in floats
#define DSTR 68

// Dynamic smem layout (bytes)
#define OFF_ZH   0        // 256 x 72 bf16  (36864)
#define OFF_ZL   36864
#define OFF_EH   73728
#define OFF_EL   110592
#define OFF_D    147456   // 256 x 68 f32   (69632)
#define OFF_ENS  217088   // float[256]
#define OFF_RED  218112   // float[256]
#define OFF_CAND 219136   // float2[256*4]  (8192)
#define OFF_HIST 227328   // int[256]
#define OFF_SP   228352   // int pos
#define SMEM_TOTAL 228368

__device__ int   g_counts[SUB];     // zero at load; vq_final re-zeroes each launch
__device__ float g_partial[NBLK];

// exact reference-rounding distance: d = R( R(zz + ee_c) - 2*ze_c )
// (bit-identical to the R2 kernel that verified at rel_err 6.5e-8)
__device__ __noinline__ float exact_d(const float* Wp, const float* zrow,
                                      float zz, int c) {
    const float4* er = (const float4*)(Wp + (size_t)c * DIM);
    float ee = 0.f, s = 0.f;
#pragma unroll
    for (int i = 0; i < 16; i++) {
        float4 q = er[i];
        ee = __fadd_rn(ee, __fmul_rn(q.x, q.x));
        ee = __fadd_rn(ee, __fmul_rn(q.y, q.y));
        ee = __fadd_rn(ee, __fmul_rn(q.z, q.z));
        ee = __fadd_rn(ee, __fmul_rn(q.w, q.w));
        s = __fmaf_rn(zrow[4*i+0], q.x, s);
        s = __fmaf_rn(zrow[4*i+1], q.y, s);
        s = __fmaf_rn(zrow[4*i+2], q.z, s);
        s = __fmaf_rn(zrow[4*i+3], q.w, s);
    }
    return __fmaf_rn(-2.f, s, __fadd_rn(zz, ee));
}

__device__ __forceinline__ void split_store(__nv_bfloat16* hi, __nv_bfloat16* lo,
                                            int base, float4 v) {
    __nv_bfloat16 h0 = __float2bfloat16(v.x), h1 = __float2bfloat16(v.y);
    __nv_bfloat16 h2 = __float2bfloat16(v.z), h3 = __float2bfloat16(v.w);
    __nv_bfloat16 l0 = __float2bfloat16(v.x - __bfloat162float(h0));
    __nv_bfloat16 l1 = __float2bfloat16(v.y - __bfloat162float(h1));
    __nv_bfloat16 l2 = __float2bfloat16(v.z - __bfloat162float(h2));
    __nv_bfloat16 l3 = __float2bfloat16(v.w - __bfloat162float(h3));
    *(__nv_bfloat162*)(hi + base)     = __nv_bfloat162{h0, h1};
    *(__nv_bfloat162*)(hi + base + 2) = __nv_bfloat162{h2, h3};
    *(__nv_bfloat162*)(lo + base)     = __nv_bfloat162{l0, l1};
    *(__nv_bfloat162*)(lo + base + 2) = __nv_bfloat162{l2, l3};
}

// ---------------- main kernel ----------------
__global__ __launch_bounds__(256, 1)
void vq_main(const float* __restrict__ z,
             const float* __restrict__ one_hot,
             const float* __restrict__ W,
             float* __restrict__ out) {
    extern __shared__ __align__(16) char sm[];
    __nv_bfloat16* ZH = (__nv_bfloat16*)(sm + OFF_ZH);
    __nv_bfloat16* ZL = (__nv_bfloat16*)(sm + OFF_ZL);
    __nv_bfloat16* EH = (__nv_bfloat16*)(sm + OFF_EH);
    __nv_bfloat16* EL = (__nv_bfloat16*)(sm + OFF_EL);
    float*  D    = (float*)(sm + OFF_D);
    float*  ens  = (float*)(sm + OFF_ENS);
    float*  red  = (float*)(sm + OFF_RED);
    float2* cand = (float2*)(sm + OFF_CAND);
    int*    hist = (int*)(sm + OFF_HIST);
    int*    spp  = (int*)(sm + OFF_SP);

    const int tid = threadIdx.x;
    const int wid = tid >> 5;

    if (tid == 0) {
        int p = 0; float m = one_hot[0];
#pragma unroll
        for (int i = 1; i < 7; i++) {
            float v = one_hot[i];
            if (v > m) { m = v; p = i; }   // strict > : first max == jnp.argmax
        }
        *spp = p;
    }
    ens[tid] = 0.f;
    hist[tid] = 0;

    // ---- zz (bit-exact XLA serial unfused chain) from this thread's global row ----
    const long row = (long)blockIdx.x * MTILE + tid;
    const float* zrow = z + (size_t)row * DIM;
    float zz = 0.f;
#pragma unroll
    for (int k = 0; k < DIM; k++) {
        float v = zrow[k];
        zz = __fadd_rn(zz, __fmul_rn(v, v));
    }

    // ---- stage z: bf16 hi/lo split into A tiles (row-major, stride 72) ----
    {
        const float4* zg = (const float4*)(z + (size_t)blockIdx.x * MTILE * DIM);
#pragma unroll
        for (int j = 0; j < 16; j++) {
            int idx = tid + 256 * j;               // over 4096 float4s
            float4 v = zg[idx];
            int r = idx >> 4, k = (idx & 15) << 2;
            split_store(ZH, ZL, r * TSTR + k, v);
        }
    }
    __syncthreads();                               // pos + ens zeros visible

    const int pos = *spp;
    const float* Wp = W + (size_t)pos * SUB * DIM;

    // ---- stage E: bf16 split into B tiles + approx ||e||^2 ----
    {
        const float4* wg = (const float4*)Wp;
#pragma unroll
        for (int j = 0; j < 16; j++) {
            int idx = tid + 256 * j;
            float4 v = wg[idx];
            int r = idx >> 4, k = (idx & 15) << 2;
            split_store(EH, EL, r * TSTR + k, v);
            atomicAdd(&ens[r], v.x*v.x + v.y*v.y + v.z*v.z + v.w*v.w);
        }
    }
    __syncthreads();

    // ---- load A fragments once (held in registers across all chunks) ----
    wmma::fragment<wmma::matrix_a, 16, 16, 16, __nv_bfloat16, wmma::row_major> aZH[2][4], aZL[2][4];
#pragma unroll
    for (int mt = 0; mt < 2; mt++)
#pragma unroll
        for (int kt = 0; kt < 4; kt++) {
            const __nv_bfloat16* ap = ZH + (32 * wid + 16 * mt) * TSTR + kt * 16;
            wmma::load_matrix_sync(aZH[mt][kt], ap, TSTR);
            wmma::load_matrix_sync(aZL[mt][kt], ap + (OFF_ZL - OFF_ZH) / 2, TSTR);
        }

    // ---- chunked GEMM + streaming scan (warp-private D scratch) ----
    float* Dw = D + 32 * wid * DSTR;               // this warp's 32 rows
    const float* Dp = D + tid * DSTR;              // this thread's scan row
    float2* cl = cand + tid * 4;
    float best = 3.402823466e38f, thr = 3.402823466e38f;
    int cnt = 0, ovf = 0;

#pragma unroll 1
    for (int cc = 0; cc < 4; cc++) {
        wmma::fragment<wmma::accumulator, 16, 16, 16, float> acc[2][4];
#pragma unroll
        for (int mt = 0; mt < 2; mt++)
#pragma unroll
            for (int nt = 0; nt < 4; nt++)
                wmma::fill_fragment(acc[mt][nt], 0.f);

#pragma unroll
        for (int nt = 0; nt < 4; nt++) {
#pragma unroll
            for (int kt = 0; kt < 4; kt++) {
                wmma::fragment<wmma::matrix_b, 16, 16, 16, __nv_bfloat16, wmma::col_major> bh, bl;
                const __nv_bfloat16* bp = EH + (cc * 64 + nt * 16) * TSTR + kt * 16;
                wmma::load_matrix_sync(bh, bp, TSTR);
                wmma::load_matrix_sync(bl, bp + (OFF_EL - OFF_EH) / 2, TSTR);
#pragma unroll
                for (int mt = 0; mt < 2; mt++) {
                    wmma::mma_sync(acc[mt][nt], aZH[mt][kt], bh, acc[mt][nt]);
                    wmma::mma_sync(acc[mt][nt], aZH[mt][kt], bl, acc[mt][nt]);
                    wmma::mma_sync(acc[mt][nt], aZL[mt][kt], bh, acc[mt][nt]);
                }
            }
        }
#pragma unroll
        for (int mt = 0; mt < 2; mt++)
#pragma unroll
            for (int nt = 0; nt < 4; nt++)
                wmma::store_matrix_sync(Dw + 16 * mt * DSTR + nt * 16,
                                        acc[mt][nt], DSTR, wmma::mem_row_major);
        __syncwarp();

        // scan this thread's 64 values (ascending code order)
#pragma unroll 4
        for (int j = 0; j < 64; j++) {
            int c = cc * 64 + j;
            float d = __fmaf_rn(-2.f, Dp[j], ens[c]);
            if (d <= thr) {
                if (d < best) { best = d; thr = best + MARGIN; }
                if (cnt == 4) {                    // compact: drop stale entries
                    int n = 0;
                    for (int i = 0; i < 4; i++) {
                        float2 e = cl[i];
                        if (e.x <= thr) cl[n++] = e;
                    }
                    cnt = n;
                }
                if (cnt < 4) { cl[cnt] = make_float2(d, (float)c); cnt++; }
                else ovf = 1;
            }
        }
        __syncwarp();                              // before next chunk overwrites D
    }

    // ---- resolve exact argmin among candidates (ascending order = first-min) ----
    int bi;
    if (ovf) {                                     // rare fallback: full exact scan
        float bd = 3.402823466e38f; bi = 0;
        for (int c = 0; c < SUB; c++) {
            float d = exact_d(Wp, zrow, zz, c);
            if (d < bd) { bd = d; bi = c; }
        }
    } else if (cnt == 1) {
        bi = (int)cl[0].y;
    } else {
        float bd = 3.402823466e38f; bi = 0;
        for (int i = 0; i < cnt; i++) {
            int c = (int)cl[i].y;
            float d = exact_d(Wp, zrow, zz, c);
            if (d < bd) { bd = d; bi = c; }
        }
    }

    out[IDX_OFF + row] = (float)bi;
    atomicAdd(&hist[bi], 1);

    // ---- loss + straight-through zq (exact reference rounding) + transpose ----
    {
        const float4* er = (const float4*)(Wp + (size_t)bi * DIM);
        const float4* zr4 = (const float4*)zrow;
        const int b = (int)(row >> 14);
        const int t = (int)(row & 16383);
        float* zo = out + ZQ_OFF + (long)b * DIM * 16384 + t;
        float s = 0.f;
#pragma unroll
        for (int i = 0; i < 16; i++) {
            float4 q = er[i];
            float4 zf = zr4[i];
            float d0 = __fsub_rn(q.x, zf.x); s += d0 * d0;
            float d1 = __fsub_rn(q.y, zf.y); s += d1 * d1;
            float d2 = __fsub_rn(q.z, zf.z); s += d2 * d2;
            float d3 = __fsub_rn(q.w, zf.w); s += d3 * d3;
            zo[(long)(4*i+0) * 16384] = __fadd_rn(zf.x, d0);
            zo[(long)(4*i+1) * 16384] = __fadd_rn(zf.y, d1);
            zo[(long)(4*i+2) * 16384] = __fadd_rn(zf.z, d2);
            zo[(long)(4*i+3) * 16384] = __fadd_rn(zf.w, d3);
        }
        red[tid] = s;
    }
    __syncthreads();
#pragma unroll
    for (int o = 128; o; o >>= 1) {
        if (tid < o) red[tid] += red[tid + o];
        __syncthreads();
    }
    if (tid == 0) g_partial[blockIdx.x] = red[0];

    atomicAdd(&g_counts[tid], hist[tid]);
}

// ---------------- final: loss scalar + perplexity (+ self-clean counts) ----------------
__global__ void vq_final(float* __restrict__ out) {
    __shared__ float red[256];
    int tid = threadIdx.x;

    float s = g_partial[tid] + g_partial[tid + 256]
            + g_partial[tid + 512] + g_partial[tid + 768];
    red[tid] = s;
    __syncthreads();
#pragma unroll
    for (int o = 128; o; o >>= 1) {
        if (tid < o) red[tid] += red[tid + o];
        __syncthreads();
    }
    float total = red[0];
    __syncthreads();

    int cnt = g_counts[tid];
    g_counts[tid] = 0;                             // stay zero for next launch
    float em = (float)cnt * (1.0f / 262144.0f);
    red[tid] = em * logf(em + 1e-10f);
    __syncthreads();
#pragma unroll
    for (int o = 128; o; o >>= 1) {
        if (tid < o) red[tid] += red[tid + o];
        __syncthreads();
    }
    if (tid == 0) {
        out[LOSS_OFF] = 1.25f * total * (1.0f / 16777216.0f);
        out[PERP_OFF] = expf(-red[0]);
    }
}

extern "C" void kernel_launch(void* const* d_in, const int* in_sizes, int n_in,
                              void* d_out, int out_size) {
    const float* z       = (const float*)d_in[0];
    const float* one_hot = (const float*)d_in[1];
    const float* W       = (const float*)d_in[2];
    float* out = (float*)d_out;

    cudaFuncSetAttribute(vq_main, cudaFuncAttributeMaxDynamicSharedMemorySize, SMEM_TOTAL);
    vq_main<<<NBLK, 256, SMEM_TOTAL>>>(z, one_hot, W, out);
    vq_final<<<1, 256>>>(out);
}

// round 14
// speedup vs baseline: 1.1045x; 1.1045x over previous
#include <cuda_runtime.h>
#include <cuda_bf16.h>
#include <mma.h>
#include <cstdint>

using namespace nvcuda;

// Problem constants
#define NROWS   262144        // 16 * 16384
#define DIM     64
#define SUB     256
#define MTILE   256           // rows per block
#define NBLK    1024          // NROWS / MTILE
#define MARGIN  3.0e-5f

// Output layout (float32): [z_q_out: 16*64*16384][loss][perplexity][idx: 262144]
#define ZQ_OFF   0
#define LOSS_OFF 16777216
#define PERP_OFF 16777217
#define IDX_OFF  16777218

// Shared bf16 tile stride (72 bf16 = 144B, 16B-aligned rows for ldmatrix)
#define TSTR 72
// D scratch stride in floats — MUST be a multiple of 4 (wmma ldm contract for f32)
#define DSTR 68

// Dynamic smem layout (bytes)
#define OFF_ZH   0        // 256 x 72 bf16  (36864)
#define OFF_ZL   36864
#define OFF_EH   73728
#define OFF_EL   110592
#define OFF_D    147456   // 256 x 68 f32   (69632)
#define OFF_ENS  217088   // float[256]
#define OFF_RED  218112   // float[256]
#define OFF_CAND 219136   // float2[256*4]  (8192)
#define OFF_HIST 227328   // int[256]
#define OFF_SP   228352   // int pos
#define SMEM_TOTAL 228368

__device__ int   g_counts[SUB];     // zero at load; vq_final re-zeroes each launch
__device__ float g_partial[NBLK];

// exact reference-rounding distance: d = R( R(zz + ee_c) - 2*ze_c )
// (bit-identical to the R2 kernel that verified at rel_err 6.5e-8)
__device__ __noinline__ float exact_d(const float* Wp, const float* zrow,
                                      float zz, int c) {
    const float4* er = (const float4*)(Wp + (size_t)c * DIM);
    float ee = 0.f, s = 0.f;
#pragma unroll
    for (int i = 0; i < 16; i++) {
        float4 q = er[i];
        ee = __fadd_rn(ee, __fmul_rn(q.x, q.x));
        ee = __fadd_rn(ee, __fmul_rn(q.y, q.y));
        ee = __fadd_rn(ee, __fmul_rn(q.z, q.z));
        ee = __fadd_rn(ee, __fmul_rn(q.w, q.w));
        s = __fmaf_rn(zrow[4*i+0], q.x, s);
        s = __fmaf_rn(zrow[4*i+1], q.y, s);
        s = __fmaf_rn(zrow[4*i+2], q.z, s);
        s = __fmaf_rn(zrow[4*i+3], q.w, s);
    }
    return __fmaf_rn(-2.f, s, __fadd_rn(zz, ee));
}

// zz = ||z||^2 with XLA's serial in-order unfused rounding (bit-exact emulation)
__device__ __noinline__ float exact_zz(const float* zrow) {
    float zz = 0.f;
#pragma unroll
    for (int k = 0; k < DIM; k++) {
        float v = zrow[k];
        zz = __fadd_rn(zz, __fmul_rn(v, v));
    }
    return zz;
}

__device__ __forceinline__ void split_store(__nv_bfloat16* hi, __nv_bfloat16* lo,
                                            int base, float4 v) {
    __nv_bfloat16 h0 = __float2bfloat16(v.x), h1 = __float2bfloat16(v.y);
    __nv_bfloat16 h2 = __float2bfloat16(v.z), h3 = __float2bfloat16(v.w);
    __nv_bfloat16 l0 = __float2bfloat16(v.x - __bfloat162float(h0));
    __nv_bfloat16 l1 = __float2bfloat16(v.y - __bfloat162float(h1));
    __nv_bfloat16 l2 = __float2bfloat16(v.z - __bfloat162float(h2));
    __nv_bfloat16 l3 = __float2bfloat16(v.w - __bfloat162float(h3));
    *(__nv_bfloat162*)(hi + base)     = __nv_bfloat162{h0, h1};
    *(__nv_bfloat162*)(hi + base + 2) = __nv_bfloat162{h2, h3};
    *(__nv_bfloat162*)(lo + base)     = __nv_bfloat162{l0, l1};
    *(__nv_bfloat162*)(lo + base + 2) = __nv_bfloat162{l2, l3};
}

// ---------------- main kernel ----------------
__global__ __launch_bounds__(256, 1)
void vq_main(const float* __restrict__ z,
             const float* __restrict__ one_hot,
             const float* __restrict__ W,
             float* __restrict__ out) {
    extern __shared__ __align__(16) char sm[];
    __nv_bfloat16* ZH = (__nv_bfloat16*)(sm + OFF_ZH);
    __nv_bfloat16* EH = (__nv_bfloat16*)(sm + OFF_EH);
    float*  D    = (float*)(sm + OFF_D);
    float*  ens  = (float*)(sm + OFF_ENS);
    float*  red  = (float*)(sm + OFF_RED);
    float2* cand = (float2*)(sm + OFF_CAND);
    int*    hist = (int*)(sm + OFF_HIST);
    int*    spp  = (int*)(sm + OFF_SP);

    const int tid = threadIdx.x;
    const int wid = tid >> 5;

    if (tid == 0) {
        int p = 0; float m = one_hot[0];
#pragma unroll
        for (int i = 1; i < 7; i++) {
            float v = one_hot[i];
            if (v > m) { m = v; p = i; }   // strict > : first max == jnp.argmax
        }
        *spp = p;
    }
    hist[tid] = 0;

    const long row = (long)blockIdx.x * MTILE + tid;
    const float* zrow = z + (size_t)row * DIM;

    // ---- stage z: bf16 hi/lo split into A tiles (row-major, stride 72) ----
    {
        __nv_bfloat16* ZL = (__nv_bfloat16*)(sm + OFF_ZL);
        const float4* zg = (const float4*)(z + (size_t)blockIdx.x * MTILE * DIM);
#pragma unroll
        for (int j = 0; j < 16; j++) {
            int idx = tid + 256 * j;               // over 4096 float4s
            float4 v = zg[idx];
            int r = idx >> 4, k = (idx & 15) << 2;
            split_store(ZH, ZL, r * TSTR + k, v);
        }
    }
    __syncthreads();                               // pos visible

    const int pos = *spp;
    const float* Wp = W + (size_t)pos * SUB * DIM;

    // ---- stage E: bf16 split into B tiles; ens[t] from own code row ----
    {
        __nv_bfloat16* EL = (__nv_bfloat16*)(sm + OFF_EL);
        const float4* wg = (const float4*)Wp;
#pragma unroll
        for (int j = 0; j < 16; j++) {
            int idx = tid + 256 * j;
            float4 v = wg[idx];
            int r = idx >> 4, k = (idx & 15) << 2;
            split_store(EH, EL, r * TSTR + k, v);
        }
        // approx ||e||^2 for own code (any accurate order; only feeds the filter)
        const float4* er = (const float4*)(Wp + (size_t)tid * DIM);
        float s = 0.f;
#pragma unroll
        for (int i = 0; i < 16; i++) {
            float4 q = er[i];
            s = __fmaf_rn(q.x, q.x, s);
            s = __fmaf_rn(q.y, q.y, s);
            s = __fmaf_rn(q.z, q.z, s);
            s = __fmaf_rn(q.w, q.w, s);
        }
        ens[tid] = s;
    }
    __syncthreads();

    // ---- chunked 3-split GEMM + streaming scan (warp-private D scratch) ----
    const int arow = 32 * wid;                     // warp's first z row in tile
    float* Dw = D + arow * DSTR;
    const float4* Dp4 = (const float4*)(D + tid * DSTR);   // 16B-aligned (68*4*tid)
    float2* cl = cand + tid * 4;
    float best = 3.402823466e38f, thr = 3.402823466e38f;
    int cnt = 0, ovf = 0;

#pragma unroll 1
    for (int cc = 0; cc < 4; cc++) {
#pragma unroll 1
        for (int mt = 0; mt < 2; mt++) {
            wmma::fragment<wmma::accumulator, 16, 16, 16, float> acc[4];
#pragma unroll
            for (int nt = 0; nt < 4; nt++)
                wmma::fill_fragment(acc[nt], 0.f);

#pragma unroll
            for (int kt = 0; kt < 4; kt++) {
                wmma::fragment<wmma::matrix_a, 16, 16, 16, __nv_bfloat16, wmma::row_major> aH, aL;
                const __nv_bfloat16* ap = ZH + (arow + 16 * mt) * TSTR + kt * 16;
                wmma::load_matrix_sync(aH, ap, TSTR);
                wmma::load_matrix_sync(aL, ap + (OFF_ZL - OFF_ZH) / 2, TSTR);
#pragma unroll
                for (int nt = 0; nt < 4; nt++) {
                    wmma::fragment<wmma::matrix_b, 16, 16, 16, __nv_bfloat16, wmma::col_major> bh, bl;
                    const __nv_bfloat16* bp = EH + (cc * 64 + nt * 16) * TSTR + kt * 16;
                    wmma::load_matrix_sync(bh, bp, TSTR);
                    wmma::load_matrix_sync(bl, bp + (OFF_EL - OFF_EH) / 2, TSTR);
                    wmma::mma_sync(acc[nt], aH, bh, acc[nt]);
                    wmma::mma_sync(acc[nt], aH, bl, acc[nt]);
                    wmma::mma_sync(acc[nt], aL, bh, acc[nt]);
                }
            }
#pragma unroll
            for (int nt = 0; nt < 4; nt++)
                wmma::store_matrix_sync(Dw + 16 * mt * DSTR + nt * 16,
                                        acc[nt], DSTR, wmma::mem_row_major);
        }
        __syncwarp();

        // scan this thread's 64 values (ascending code order => first-min)
#pragma unroll
        for (int q4 = 0; q4 < 16; q4++) {
            float4 v = Dp4[q4];
            float dv[4] = {v.x, v.y, v.z, v.w};
#pragma unroll
            for (int u = 0; u < 4; u++) {
                int c = cc * 64 + q4 * 4 + u;
                float d = __fmaf_rn(-2.f, dv[u], ens[c]);
                if (d <= thr) {
                    if (d < best) { best = d; thr = best + MARGIN; }
                    if (cnt == 4) {                // compact: drop stale entries
                        int n = 0;
                        for (int i = 0; i < 4; i++) {
                            float2 e = cl[i];
                            if (e.x <= thr) cl[n++] = e;
                        }
                        cnt = n;
                    }
                    if (cnt < 4) { cl[cnt] = make_float2(d, (float)c); cnt++; }
                    else ovf = 1;
                }
            }
        }
        __syncwarp();                              // before next chunk overwrites D
    }

    // ---- resolve exact argmin among candidates (ascending order = first-min) ----
    int bi;
    if (ovf) {                                     // rare fallback: full exact scan
        float zz = exact_zz(zrow);
        float bd = 3.402823466e38f; bi = 0;
        for (int c = 0; c < SUB; c++) {
            float d = exact_d(Wp, zrow, zz, c);
            if (d < bd) { bd = d; bi = c; }
        }
    } else if (cnt == 1) {
        bi = (int)cl[0].y;                         // unambiguous: no exact eval needed
    } else {
        float zz = exact_zz(zrow);
        float bd = 3.402823466e38f; bi = 0;
        for (int i = 0; i < cnt; i++) {
            int c = (int)cl[i].y;
            float d = exact_d(Wp, zrow, zz, c);
            if (d < bd) { bd = d; bi = c; }
        }
    }

    out[IDX_OFF + row] = (float)bi;
    atomicAdd(&hist[bi], 1);

    // ---- loss + straight-through zq (exact reference rounding) + transpose ----
    {
        const float4* er = (const float4*)(Wp + (size_t)bi * DIM);
        const float4* zr4 = (const float4*)zrow;
        const int b = (int)(row >> 14);
        const int t = (int)(row & 16383);
        float* zo = out + ZQ_OFF + (long)b * DIM * 16384 + t;
        float s = 0.f;
#pragma unroll
        for (int i = 0; i < 16; i++) {
            float4 q = er[i];
            float4 zf = zr4[i];
            float d0 = __fsub_rn(q.x, zf.x); s += d0 * d0;
            float d1 = __fsub_rn(q.y, zf.y); s += d1 * d1;
            float d2 = __fsub_rn(q.z, zf.z); s += d2 * d2;
            float d3 = __fsub_rn(q.w, zf.w); s += d3 * d3;
            zo[(long)(4*i+0) * 16384] = __fadd_rn(zf.x, d0);
            zo[(long)(4*i+1) * 16384] = __fadd_rn(zf.y, d1);
            zo[(long)(4*i+2) * 16384] = __fadd_rn(zf.z, d2);
            zo[(long)(4*i+3) * 16384] = __fadd_rn(zf.w, d3);
        }
        red[tid] = s;
    }
    __syncthreads();
#pragma unroll
    for (int o = 128; o; o >>= 1) {
        if (tid < o) red[tid] += red[tid + o];
        __syncthreads();
    }
    if (tid == 0) g_partial[blockIdx.x] = red[0];

    atomicAdd(&g_counts[tid], hist[tid]);
}

// ---------------- final: loss scalar + perplexity (+ self-clean counts) ----------------
__global__ void vq_final(float* __restrict__ out) {
    __shared__ float red[256];
    int tid = threadIdx.x;

    float s = g_partial[tid] + g_partial[tid + 256]
            + g_partial[tid + 512] + g_partial[tid + 768];
    red[tid] = s;
    __syncthreads();
#pragma unroll
    for (int o = 128; o; o >>= 1) {
        if (tid < o) red[tid] += red[tid + o];
        __syncthreads();
    }
    float total = red[0];
    __syncthreads();

    int cnt = g_counts[tid];
    g_counts[tid] = 0;                             // stay zero for next launch
    float em = (float)cnt * (1.0f / 262144.0f);
    red[tid] = em * logf(em + 1e-10f);
    __syncthreads();
#pragma unroll
    for (int o = 128; o; o >>= 1) {
        if (tid < o) red[tid] += red[tid + o];
        __syncthreads();
    }
    if (tid == 0) {
        out[LOSS_OFF] = 1.25f * total * (1.0f / 16777216.0f);
        out[PERP_OFF] = expf(-red[0]);
    }
}

extern "C" void kernel_launch(void* const* d_in, const int* in_sizes, int n_in,
                              void* d_out, int out_size) {
    const float* z       = (const float*)d_in[0];
    const float* one_hot = (const float*)d_in[1];
    const float* W       = (const float*)d_in[2];
    float* out = (float*)d_out;

    cudaFuncSetAttribute(vq_main, cudaFuncAttributeMaxDynamicSharedMemorySize, SMEM_TOTAL);
    vq_main<<<NBLK, 256, SMEM_TOTAL>>>(z, one_hot, W, out);
    vq_final<<<1, 256>>>(out);
}